// round 1
// baseline (speedup 1.0000x reference)
#include <cuda_runtime.h>
#include <cuda_bf16.h>
#include <math.h>

// ----------------------------------------------------------------------------
// Problem constants
//   x:      [2, 2048, 1024] fp32
//   w_q:    [1024, 1024], w_kv: [1024, 2048], w_out: [1024, 1024]
//   b_out:  [1024], gamma/beta: [1024]
//   out:    [2, 2048, 1024] fp32
// ----------------------------------------------------------------------------
#define BATCH  2
#define SEQ    2048
#define DIM    1024
#define HEADS  16
#define DHEAD  64
#define INNER  1024
#define ROWS   (BATCH * SEQ)        // 4096
#define ATT_SCALE 0.125f            // 64^-0.5

// Scratch (device globals — no allocation allowed in kernel_launch)
__device__ float g_xn  [ROWS * DIM];        // layernormed x
__device__ float g_q   [ROWS * INNER];      // q projection
__device__ float g_kv  [ROWS * 2 * INNER];  // k|v projection
__device__ float g_attn[ROWS * INNER];      // attention output

// ----------------------------------------------------------------------------
// LayerNorm: one block per row of 1024, 256 threads, float4 per thread
// ----------------------------------------------------------------------------
__global__ void ln_kernel(const float* __restrict__ x,
                          const float* __restrict__ gamma,
                          const float* __restrict__ beta,
                          float* __restrict__ xn) {
    int row = blockIdx.x;
    int t   = threadIdx.x;            // 256
    const float* xr = x + (size_t)row * DIM;

    float4 v = *(const float4*)&xr[t * 4];
    float s  = v.x + v.y + v.z + v.w;
    float s2 = v.x*v.x + v.y*v.y + v.z*v.z + v.w*v.w;

    #pragma unroll
    for (int o = 16; o; o >>= 1) {
        s  += __shfl_xor_sync(0xffffffffu, s,  o);
        s2 += __shfl_xor_sync(0xffffffffu, s2, o);
    }
    __shared__ float sh1[8], sh2[8];
    int w = t >> 5, l = t & 31;
    if (l == 0) { sh1[w] = s; sh2[w] = s2; }
    __syncthreads();
    float ts = 0.f, ts2 = 0.f;
    #pragma unroll
    for (int i = 0; i < 8; i++) { ts += sh1[i]; ts2 += sh2[i]; }

    float mean = ts * (1.0f / DIM);
    float var  = ts2 * (1.0f / DIM) - mean * mean;
    float rstd = rsqrtf(var + 1e-5f);

    float4 g = *(const float4*)&gamma[t * 4];
    float4 bb = *(const float4*)&beta[t * 4];
    float4 o;
    o.x = (v.x - mean) * rstd * g.x + bb.x;
    o.y = (v.y - mean) * rstd * g.y + bb.y;
    o.z = (v.z - mean) * rstd * g.z + bb.z;
    o.w = (v.w - mean) * rstd * g.w + bb.w;
    *(float4*)&xn[(size_t)row * DIM + t * 4] = o;
}

// ----------------------------------------------------------------------------
// SGEMM: C[M,N] = A[M,K] @ B[K,N] (+ bias[N]); 128x128x8 tiles, 256 thr, 8x8/thr
// M,N multiples of 128; K multiple of 8. All shapes here satisfy that.
// ----------------------------------------------------------------------------
__global__ __launch_bounds__(256) void sgemm_kernel(
    const float* __restrict__ A, const float* __restrict__ B,
    float* __restrict__ C, const float* __restrict__ bias,
    int M, int N, int K) {
    __shared__ float As[8][128];
    __shared__ float Bs[8][128];

    int t  = threadIdx.x;
    int bm = blockIdx.y * 128;
    int bn = blockIdx.x * 128;

    int arow = t >> 1, acol = (t & 1) * 4;   // A tile 128x8, float4 each
    int brow = t >> 5, bcol = (t & 31) * 4;  // B tile 8x128, float4 each
    int ty = t >> 4, tx = t & 15;

    float acc[8][8];
    #pragma unroll
    for (int i = 0; i < 8; i++)
        #pragma unroll
        for (int j = 0; j < 8; j++) acc[i][j] = 0.f;

    for (int k0 = 0; k0 < K; k0 += 8) {
        float4 av = *(const float4*)&A[(size_t)(bm + arow) * K + k0 + acol];
        As[acol + 0][arow] = av.x;
        As[acol + 1][arow] = av.y;
        As[acol + 2][arow] = av.z;
        As[acol + 3][arow] = av.w;
        float4 bv = *(const float4*)&B[(size_t)(k0 + brow) * N + bn + bcol];
        *(float4*)&Bs[brow][bcol] = bv;
        __syncthreads();

        #pragma unroll
        for (int kk = 0; kk < 8; kk++) {
            float a[8], b[8];
            #pragma unroll
            for (int i = 0; i < 8; i++) a[i] = As[kk][ty * 8 + i];
            #pragma unroll
            for (int j = 0; j < 8; j++) b[j] = Bs[kk][tx * 8 + j];
            #pragma unroll
            for (int i = 0; i < 8; i++)
                #pragma unroll
                for (int j = 0; j < 8; j++) acc[i][j] += a[i] * b[j];
        }
        __syncthreads();
    }

    #pragma unroll
    for (int i = 0; i < 8; i++) {
        size_t row = bm + ty * 8 + i;
        #pragma unroll
        for (int j = 0; j < 8; j += 4) {
            int col = bn + tx * 8 + j;
            float4 v = make_float4(acc[i][j], acc[i][j+1], acc[i][j+2], acc[i][j+3]);
            if (bias) {
                v.x += bias[col];   v.y += bias[col+1];
                v.z += bias[col+2]; v.w += bias[col+3];
            }
            *(float4*)&C[row * N + col] = v;
        }
    }
}

// ----------------------------------------------------------------------------
// Flash attention: grid (32 q-tiles, 32 bh), 256 threads.
// 64x64 tiles, online softmax; each thread owns a 4x4 score/out microtile.
// q:   [b, n, h*64+d]  (g_q)
// kv:  [b, n, (k|v) 2048], k at col h*64+d, v at col 1024+h*64+d
// o:   [b, n, h*64+d]  (g_attn)
// ----------------------------------------------------------------------------
#define STR 65   // smem row stride (floats)

__global__ __launch_bounds__(256) void attn_kernel(
    const float* __restrict__ q, const float* __restrict__ kv,
    float* __restrict__ o) {
    extern __shared__ float sm[];
    float* Qs = sm;                  // 64 x STR
    float* Ks = Qs + 64 * STR;
    float* Vs = Ks + 64 * STR;
    float* Ps = Vs + 64 * STR;

    int bh = blockIdx.y;
    int b  = bh >> 4, h = bh & 15;
    int q0 = blockIdx.x * 64;
    int t  = threadIdx.x;
    int ty = t >> 4, tx = t & 15;

    // Load Q tile (64 rows x 64 dims)
    for (int i = t; i < 1024; i += 256) {
        int r = i >> 4, d4 = (i & 15) << 2;
        float4 v = *(const float4*)&q[((size_t)(b * SEQ + q0 + r)) * INNER + h * DHEAD + d4];
        float* p = &Qs[r * STR + d4];
        p[0] = v.x; p[1] = v.y; p[2] = v.z; p[3] = v.w;
    }

    float m_i[4], l_i[4], acc[4][4];
    #pragma unroll
    for (int i = 0; i < 4; i++) {
        m_i[i] = -1e30f; l_i[i] = 0.f;
        #pragma unroll
        for (int j = 0; j < 4; j++) acc[i][j] = 0.f;
    }

    for (int j0 = 0; j0 < SEQ; j0 += 64) {
        __syncthreads();   // previous iter's Ks/Vs/Ps reads done
        for (int i = t; i < 1024; i += 256) {
            int r = i >> 4, d4 = (i & 15) << 2;
            size_t base = ((size_t)(b * SEQ + j0 + r)) * (2 * INNER) + h * DHEAD + d4;
            float4 kk = *(const float4*)&kv[base];
            float4 vv = *(const float4*)&kv[base + INNER];
            float* pk = &Ks[r * STR + d4];
            pk[0] = kk.x; pk[1] = kk.y; pk[2] = kk.z; pk[3] = kk.w;
            float* pv = &Vs[r * STR + d4];
            pv[0] = vv.x; pv[1] = vv.y; pv[2] = vv.z; pv[3] = vv.w;
        }
        __syncthreads();

        // S = Q K^T (4x4 microtile per thread)
        float s[4][4];
        #pragma unroll
        for (int i = 0; i < 4; i++)
            #pragma unroll
            for (int j = 0; j < 4; j++) s[i][j] = 0.f;

        #pragma unroll 8
        for (int d = 0; d < 64; d++) {
            float a[4], bb[4];
            #pragma unroll
            for (int i = 0; i < 4; i++) a[i]  = Qs[(ty * 4 + i) * STR + d];
            #pragma unroll
            for (int j = 0; j < 4; j++) bb[j] = Ks[(tx * 4 + j) * STR + d];
            #pragma unroll
            for (int i = 0; i < 4; i++)
                #pragma unroll
                for (int j = 0; j < 4; j++) s[i][j] += a[i] * bb[j];
        }

        // online softmax per row (rows replicated across the 16 tx threads)
        #pragma unroll
        for (int i = 0; i < 4; i++) {
            float mx = -1e30f;
            #pragma unroll
            for (int j = 0; j < 4; j++) {
                s[i][j] *= ATT_SCALE;
                mx = fmaxf(mx, s[i][j]);
            }
            #pragma unroll
            for (int off = 8; off; off >>= 1)
                mx = fmaxf(mx, __shfl_xor_sync(0xffffffffu, mx, off));
            float mn = fmaxf(m_i[i], mx);
            float alpha = __expf(m_i[i] - mn);
            m_i[i] = mn;
            float rs = 0.f;
            #pragma unroll
            for (int j = 0; j < 4; j++) {
                s[i][j] = __expf(s[i][j] - mn);
                rs += s[i][j];
            }
            #pragma unroll
            for (int off = 8; off; off >>= 1)
                rs += __shfl_xor_sync(0xffffffffu, rs, off);
            l_i[i] = l_i[i] * alpha + rs;
            #pragma unroll
            for (int j = 0; j < 4; j++) acc[i][j] *= alpha;
            #pragma unroll
            for (int j = 0; j < 4; j++)
                Ps[(ty * 4 + i) * STR + tx * 4 + j] = s[i][j];
        }
        __syncthreads();

        // acc += P @ V  (out cols owned: tx*4 .. tx*4+3)
        #pragma unroll 4
        for (int j = 0; j < 64; j++) {
            float vv[4], pp[4];
            #pragma unroll
            for (int c = 0; c < 4; c++) vv[c] = Vs[j * STR + tx * 4 + c];
            #pragma unroll
            for (int i = 0; i < 4; i++) pp[i] = Ps[(ty * 4 + i) * STR + j];
            #pragma unroll
            for (int i = 0; i < 4; i++)
                #pragma unroll
                for (int c = 0; c < 4; c++) acc[i][c] += pp[i] * vv[c];
        }
    }

    #pragma unroll
    for (int i = 0; i < 4; i++) {
        float inv = 1.f / l_i[i];
        int r = q0 + ty * 4 + i;
        #pragma unroll
        for (int c = 0; c < 4; c++)
            o[((size_t)(b * SEQ + r)) * INNER + h * DHEAD + tx * 4 + c] = acc[i][c] * inv;
    }
}

// ----------------------------------------------------------------------------
// Launch
// ----------------------------------------------------------------------------
extern "C" void kernel_launch(void* const* d_in, const int* in_sizes, int n_in,
                              void* d_out, int out_size) {
    const float* x     = (const float*)d_in[0];
    const float* w_q   = (const float*)d_in[1];
    const float* w_kv  = (const float*)d_in[2];
    const float* w_out = (const float*)d_in[3];
    const float* b_out = (const float*)d_in[4];
    const float* gamma = (const float*)d_in[5];
    const float* beta  = (const float*)d_in[6];
    float* out = (float*)d_out;

    void *p_xn, *p_q, *p_kv, *p_attn;
    cudaGetSymbolAddress(&p_xn,   g_xn);
    cudaGetSymbolAddress(&p_q,    g_q);
    cudaGetSymbolAddress(&p_kv,   g_kv);
    cudaGetSymbolAddress(&p_attn, g_attn);
    float* xn   = (float*)p_xn;
    float* qb   = (float*)p_q;
    float* kvb  = (float*)p_kv;
    float* attn = (float*)p_attn;

    const int attn_smem = 4 * 64 * STR * (int)sizeof(float);  // 66560 B
    cudaFuncSetAttribute(attn_kernel,
                         cudaFuncAttributeMaxDynamicSharedMemorySize, attn_smem);

    // 1) LayerNorm
    ln_kernel<<<ROWS, 256>>>(x, gamma, beta, xn);

    // 2) Q and KV projections
    sgemm_kernel<<<dim3(INNER / 128, ROWS / 128), 256>>>(
        xn, w_q, qb, nullptr, ROWS, INNER, DIM);
    sgemm_kernel<<<dim3((2 * INNER) / 128, ROWS / 128), 256>>>(
        xn, w_kv, kvb, nullptr, ROWS, 2 * INNER, DIM);

    // 3) Flash attention
    attn_kernel<<<dim3(SEQ / 64, BATCH * HEADS), 256, attn_smem>>>(qb, kvb, attn);

    // 4) Output projection + bias
    sgemm_kernel<<<dim3(DIM / 128, ROWS / 128), 256>>>(
        attn, w_out, out, b_out, ROWS, DIM, DIM);
}